// round 1
// baseline (speedup 1.0000x reference)
#include <cuda_runtime.h>
#include <cstdint>
#include <cstddef>
#include <math.h>

// ---------------- problem constants ----------------
#define N_NODES 50000
#define N_EDGES 1600000
#define G_EMB   128
#define L_EMB   256
#define HID     256
#define SEQ     2048
#define TGT     16
#define LSTM_T  (SEQ - TGT)          // 2032
#define GATES   (4 * HID)            // 1024

// output layout (float32, concatenated in tuple order)
#define HH_ELEMS  ((size_t)LSTM_T * 2 * HID)   // 2032*512 = 1040384
#define GCN_OFF   HH_ELEMS
#define H1_OFF    (GCN_OFF + HID)              // 1040640
#define C1_OFF    (H1_OFF + 2 * HID)           // 1041152

// ---------------- scratch (device globals; no runtime alloc allowed) ----------------
__device__ float g_aggF[(size_t)N_NODES * G_EMB];      // 25.6 MB
__device__ float g_X[(size_t)2 * LSTM_T * GATES];      // 16.6 MB  (Xf then Xb)
__device__ float g_gcn_sum[HID];

// ---------------- helpers ----------------
__device__ __forceinline__ uint32_t smem_u32(const void* p) {
    uint32_t a;
    asm("{ .reg .u64 t; cvta.to.shared.u64 t, %1; cvt.u32.u64 %0, t; }"
        : "=r"(a) : "l"(p));
    return a;
}
__device__ __forceinline__ float sigmoidf_(float x) {
    return 1.0f / (1.0f + expf(-x));
}
#define CLUSTER_SYNC() do { \
    asm volatile("barrier.cluster.arrive.aligned;" ::: "memory"); \
    asm volatile("barrier.cluster.wait.aligned;"   ::: "memory"); \
} while (0)

// ---------------- K1: zero scratch ----------------
__global__ void k_zero() {
    size_t n = (size_t)N_NODES * G_EMB;
    size_t stride = (size_t)gridDim.x * blockDim.x;
    for (size_t i = (size_t)blockIdx.x * blockDim.x + threadIdx.x; i < n; i += stride)
        g_aggF[i] = 0.0f;
    size_t t = (size_t)blockIdx.x * blockDim.x + threadIdx.x;
    if (t < HID) g_gcn_sum[t] = 0.0f;
}

// ---------------- K2: edge scatter  aggF[row] += w * emb_loc_graph[loc_train[col]] ----------------
__global__ void k_edge_scatter(const int* __restrict__ edge_index,
                               const float* __restrict__ edge_weight,
                               const int* __restrict__ loc_train,
                               const float* __restrict__ emb_loc_graph) {
    int gtid  = blockIdx.x * blockDim.x + threadIdx.x;
    int warp  = gtid >> 5;
    int lane  = gtid & 31;
    int nwarp = (gridDim.x * blockDim.x) >> 5;
    for (int e = warp; e < N_EDGES; e += nwarp) {
        int   rr = edge_index[e];
        int   cc = edge_index[N_EDGES + e];
        float wv = edge_weight[e];
        int   nd = loc_train[cc];
        float4 f4 = __ldg((const float4*)(emb_loc_graph + (size_t)nd * G_EMB) + lane);
        float* dst = g_aggF + (size_t)rr * G_EMB + lane * 4;
        atomicAdd(dst + 0, wv * f4.x);
        atomicAdd(dst + 1, wv * f4.y);
        atomicAdd(dst + 2, wv * f4.z);
        atomicAdd(dst + 3, wv * f4.w);
    }
}

// ---------------- K3: per-node  relu(aggF @ gc_w + b)  accumulated for mean ----------------
__global__ void __launch_bounds__(256) k_gcn_gemm(const float* __restrict__ gc_w,
                                                  const float* __restrict__ gc_b) {
    __shared__ float4 a_s[G_EMB / 4];   // one node's 128-float aggF row
    int tid = threadIdx.x;              // column j of HID
    float wcol[G_EMB];
    #pragma unroll
    for (int k = 0; k < G_EMB; k++) wcol[k] = __ldg(gc_w + (size_t)k * HID + tid);
    float bj = __ldg(gc_b + tid);

    float msum = 0.0f;
    for (int n = blockIdx.x; n < N_NODES; n += gridDim.x) {
        __syncthreads();
        if (tid < G_EMB / 4)
            a_s[tid] = ((const float4*)(g_aggF + (size_t)n * G_EMB))[tid];
        __syncthreads();
        float acc0 = bj, acc1 = 0.0f;
        #pragma unroll
        for (int k4 = 0; k4 < G_EMB / 4; k4++) {
            float4 a4 = a_s[k4];
            acc0 = fmaf(a4.x, wcol[4 * k4 + 0], acc0);
            acc1 = fmaf(a4.y, wcol[4 * k4 + 1], acc1);
            acc0 = fmaf(a4.z, wcol[4 * k4 + 2], acc0);
            acc1 = fmaf(a4.w, wcol[4 * k4 + 3], acc1);
        }
        msum += fmaxf(acc0 + acc1, 0.0f);
    }
    atomicAdd(&g_gcn_sum[tid], msum);
}

// ---------------- K4: precompute gate inputs X[t,g] = x_t . Wih[g] + bih[g] + bhh[g] ----------------
__global__ void __launch_bounds__(256) k_xgemm(const int* __restrict__ loc,
                                               const float* __restrict__ emb_loc,
                                               const float* __restrict__ Wih_f,
                                               const float* __restrict__ bih_f,
                                               const float* __restrict__ bhh_f,
                                               const float* __restrict__ Wih_b,
                                               const float* __restrict__ bih_b,
                                               const float* __restrict__ bhh_b) {
    int dir = blockIdx.y;
    int t0  = blockIdx.x * 16;
    const float* Wih = dir ? Wih_b : Wih_f;
    const float* b1  = dir ? bih_b : bih_f;
    const float* b2  = dir ? bhh_b : bhh_f;
    float* Xd = g_X + (size_t)dir * LSTM_T * GATES;

    __shared__ float xs[16][L_EMB];
    __shared__ int   locv[16];
    int tid = threadIdx.x;
    if (tid < 16) {
        int t  = t0 + tid;
        int tt = dir ? (LSTM_T - 1 - t) : t;
        locv[tid] = loc[tt];
    }
    __syncthreads();
    for (int tl = 0; tl < 16; tl++)
        xs[tl][tid] = __ldg(emb_loc + (size_t)locv[tl] * L_EMB + tid);
    __syncthreads();

    for (int gq = 0; gq < 4; gq++) {
        int g = gq * 256 + tid;
        const float4* wr = (const float4*)(Wih + (size_t)g * L_EMB);
        float acc[16];
        #pragma unroll
        for (int i = 0; i < 16; i++) acc[i] = 0.0f;
        #pragma unroll 4
        for (int k4 = 0; k4 < L_EMB / 4; k4++) {
            float4 w4 = __ldg(wr + k4);
            #pragma unroll
            for (int tl = 0; tl < 16; tl++) {
                float4 x4 = ((const float4*)xs[tl])[k4];
                acc[tl] = fmaf(w4.x, x4.x, fmaf(w4.y, x4.y,
                           fmaf(w4.z, x4.z, fmaf(w4.w, x4.w, acc[tl]))));
            }
        }
        float bsum = __ldg(b1 + g) + __ldg(b2 + g);
        for (int tl = 0; tl < 16; tl++)
            Xd[(size_t)(t0 + tl) * GATES + g] = acc[tl] + bsum;
    }
}

// ---------------- K5: bidirectional LSTM recurrence ----------------
// grid = 16 CTAs, cluster = 8. Cluster 0 = forward, cluster 1 = backward.
// Each CTA owns 32 h-dims (4 gate rows each = 128 rows of Whh, kept in registers:
// 512 threads x 64 fp32). h is broadcast every step via DSMEM + cluster.sync.
#define CL  8
__global__ void __cluster_dims__(CL, 1, 1) __launch_bounds__(512, 1)
k_lstm(const float* __restrict__ Whh_f, const float* __restrict__ Whh_b,
       float* __restrict__ out) {
    // h buffer: 4 quarters of 64 floats, padded to stride 68 (bank-conflict-free)
    __shared__ float h_s[2][4 * 68];
    __shared__ float gates_s[128];

    int dir = blockIdx.x / CL;
    uint32_t r;
    asm("mov.u32 %0, %%cluster_ctarank;" : "=r"(r));

    const float* Whh = dir ? Whh_b : Whh_f;
    const float* Xd  = g_X + (size_t)dir * LSTM_T * GATES;

    int tid = threadIdx.x;
    int gi  = tid >> 2;            // 0..127 local gate row
    int c   = tid & 3;             // column quarter (64 cols)
    int q   = gi >> 5;             // gate type i/f/g/o
    int d   = gi & 31;             // h-dim within this CTA
    int grow = q * HID + (int)r * 32 + d;   // global gate row

    // load this thread's 64 Whh weights into registers
    float w[64];
    {
        const float4* wp = (const float4*)(Whh + (size_t)grow * HID + c * 64);
        #pragma unroll
        for (int i = 0; i < 16; i++) {
            float4 t4 = __ldg(wp + i);
            w[4 * i + 0] = t4.x; w[4 * i + 1] = t4.y;
            w[4 * i + 2] = t4.z; w[4 * i + 3] = t4.w;
        }
    }

    for (int i = tid; i < 2 * 4 * 68; i += blockDim.x)
        (&h_s[0][0])[i] = 0.0f;
    float creg = 0.0f;
    __syncthreads();
    CLUSTER_SYNC();   // all buffers zeroed before any peer writes

    int bufp = 0;
    for (int t = 0; t < LSTM_T; t++) {
        float xv = 0.0f;
        if (c == 0) xv = __ldg(Xd + (size_t)t * GATES + grow);

        const float4* hp = (const float4*)(h_s[bufp] + c * 68);
        float a0 = 0.f, a1 = 0.f, a2 = 0.f, a3 = 0.f;
        #pragma unroll
        for (int i = 0; i < 16; i++) {
            float4 hv = hp[i];
            a0 = fmaf(w[4 * i + 0], hv.x, a0);
            a1 = fmaf(w[4 * i + 1], hv.y, a1);
            a2 = fmaf(w[4 * i + 2], hv.z, a2);
            a3 = fmaf(w[4 * i + 3], hv.w, a3);
        }
        float v = (a0 + a1) + (a2 + a3);
        v += __shfl_xor_sync(0xffffffffu, v, 1);
        v += __shfl_xor_sync(0xffffffffu, v, 2);
        if (c == 0) gates_s[gi] = v + xv;
        __syncthreads();

        int bufn = bufp ^ 1;
        if (tid < 32) {
            float pi = gates_s[tid];
            float pf = gates_s[32 + tid];
            float pg = gates_s[64 + tid];
            float po = gates_s[96 + tid];
            float iv = sigmoidf_(pi);
            float fv = sigmoidf_(pf);
            float gv = tanhf(pg);
            float ov = sigmoidf_(po);
            creg = fv * creg + iv * gv;
            float hn = ov * tanhf(creg);

            int hidx = (int)r * 32 + tid;   // global h index 0..255
            size_t orow = (dir == 0)
                        ? (size_t)t * (2 * HID) + hidx
                        : (size_t)(LSTM_T - 1 - t) * (2 * HID) + HID + hidx;
            out[orow] = hn;
            if (t == LSTM_T - 1) {
                out[H1_OFF + (size_t)dir * HID + hidx] = hn;
                out[C1_OFF + (size_t)dir * HID + hidx] = creg;
            }

            // broadcast hn into every cluster CTA's next h buffer
            int quarter = hidx >> 6;
            int pos     = hidx & 63;
            uint32_t laddr = smem_u32(&h_s[bufn][quarter * 68 + pos]);
            #pragma unroll
            for (int p = 0; p < CL; p++) {
                uint32_t pa;
                asm volatile("mapa.shared::cluster.u32 %0, %1, %2;"
                             : "=r"(pa) : "r"(laddr), "r"(p));
                asm volatile("st.shared::cluster.f32 [%0], %1;"
                             :: "r"(pa), "f"(hn) : "memory");
            }
        }
        CLUSTER_SYNC();
        bufp = bufn;
    }
}

// ---------------- K6: finalize gcn mean ----------------
__global__ void k_gcn_final(float* __restrict__ out) {
    int tid = threadIdx.x;
    if (tid < HID)
        out[GCN_OFF + tid] = g_gcn_sum[tid] * (1.0f / (float)N_NODES);
}

// ---------------- launch ----------------
extern "C" void kernel_launch(void* const* d_in, const int* in_sizes, int n_in,
                              void* d_out, int out_size) {
    // input index map; target_len (scalar, size 1) may or may not be present at slot 4
    int o = (n_in > 4 && in_sizes[4] == 1) ? 1 : 0;
    const int*   loc           = (const int*)  d_in[0];
    const int*   loc_train     = (const int*)  d_in[1];
    const int*   edge_index    = (const int*)  d_in[2];
    const float* edge_weight   = (const float*)d_in[3];
    const float* emb_loc       = (const float*)d_in[4 + o];
    const float* emb_loc_graph = (const float*)d_in[5 + o];
    const float* gc_w          = (const float*)d_in[6 + o];
    const float* gc_b          = (const float*)d_in[7 + o];
    const float* Wih_f         = (const float*)d_in[8 + o];
    const float* Whh_f         = (const float*)d_in[9 + o];
    const float* bih_f         = (const float*)d_in[10 + o];
    const float* bhh_f         = (const float*)d_in[11 + o];
    const float* Wih_b         = (const float*)d_in[12 + o];
    const float* Whh_b         = (const float*)d_in[13 + o];
    const float* bih_b         = (const float*)d_in[14 + o];
    const float* bhh_b         = (const float*)d_in[15 + o];
    float* out = (float*)d_out;

    k_zero<<<256, 256>>>();
    k_edge_scatter<<<2048, 256>>>(edge_index, edge_weight, loc_train, emb_loc_graph);
    k_xgemm<<<dim3(LSTM_T / 16, 2), 256>>>(loc, emb_loc,
                                           Wih_f, bih_f, bhh_f,
                                           Wih_b, bih_b, bhh_b);
    k_gcn_gemm<<<148, 256>>>(gc_w, gc_b);
    k_lstm<<<16, 512>>>(Whh_f, Whh_b, out);
    k_gcn_final<<<1, 256>>>(out);
}

// round 4
// speedup vs baseline: 1.0819x; 1.0819x over previous
#include <cuda_runtime.h>
#include <cstdint>
#include <cstddef>
#include <math.h>

// ---------------- problem constants ----------------
#define N_NODES 50000
#define N_EDGES 1600000
#define G_EMB   128
#define L_EMB   256
#define HID     256
#define SEQ     2048
#define TGT     16
#define LSTM_T  (SEQ - TGT)          // 2032
#define GATES   (4 * HID)            // 1024

// output layout (float32, concatenated in tuple order)
#define HH_ELEMS  ((size_t)LSTM_T * 2 * HID)   // 2032*512 = 1040384
#define GCN_OFF   HH_ELEMS
#define H1_OFF    (GCN_OFF + HID)              // 1040640
#define C1_OFF    (H1_OFF + 2 * HID)           // 1041152

// ---------------- scratch (device globals; no runtime alloc allowed) ----------------
__device__ float g_aggF[(size_t)N_NODES * G_EMB];      // 25.6 MB
__device__ float g_X[(size_t)2 * LSTM_T * GATES];      // 16.6 MB  (Xf then Xb)
__device__ float g_gcn_sum[HID];

// ---------------- helpers ----------------
__device__ __forceinline__ uint32_t smem_u32(const void* p) {
    uint32_t a;
    asm("{ .reg .u64 t; cvta.to.shared.u64 t, %1; cvt.u32.u64 %0, t; }"
        : "=r"(a) : "l"(p));
    return a;
}
// clamped fast sigmoid / tanh: MUFU-based, safe at saturation, ~1e-6 rel err
__device__ __forceinline__ float fsig(float x) {
    float xc = fminf(fmaxf(x, -20.0f), 20.0f);
    return __fdividef(1.0f, 1.0f + __expf(-xc));
}
__device__ __forceinline__ float ftanh(float x) {
    float xc = fminf(fmaxf(x, -15.0f), 15.0f);
    return __fdividef(2.0f, 1.0f + __expf(-2.0f * xc)) - 1.0f;
}
#define CLUSTER_SYNC() do { \
    asm volatile("barrier.cluster.arrive.aligned;" ::: "memory"); \
    asm volatile("barrier.cluster.wait.aligned;"   ::: "memory"); \
} while (0)

// ---------------- K1: zero scratch (vectorized) ----------------
__global__ void k_zero() {
    size_t n4 = (size_t)N_NODES * G_EMB / 4;
    size_t stride = (size_t)gridDim.x * blockDim.x;
    float4 z = make_float4(0.f, 0.f, 0.f, 0.f);
    for (size_t i = (size_t)blockIdx.x * blockDim.x + threadIdx.x; i < n4; i += stride)
        ((float4*)g_aggF)[i] = z;
    size_t t = (size_t)blockIdx.x * blockDim.x + threadIdx.x;
    if (t < HID) g_gcn_sum[t] = 0.0f;
}

// ---------------- K2: edge scatter  aggF[row] += w * emb_loc_graph[loc_train[col]] ----------------
__global__ void k_edge_scatter(const int* __restrict__ edge_index,
                               const float* __restrict__ edge_weight,
                               const int* __restrict__ loc_train,
                               const float* __restrict__ emb_loc_graph) {
    int gtid  = blockIdx.x * blockDim.x + threadIdx.x;
    int warp  = gtid >> 5;
    int lane  = gtid & 31;
    int nwarp = (gridDim.x * blockDim.x) >> 5;
    for (int e = warp; e < N_EDGES; e += nwarp) {
        int   rr = edge_index[e];
        int   cc = edge_index[N_EDGES + e];
        float wv = edge_weight[e];
        int   nd = loc_train[cc];
        float4 f4 = __ldg((const float4*)(emb_loc_graph + (size_t)nd * G_EMB) + lane);
        float* dst = g_aggF + (size_t)rr * G_EMB + lane * 4;
        atomicAdd(dst + 0, wv * f4.x);
        atomicAdd(dst + 1, wv * f4.y);
        atomicAdd(dst + 2, wv * f4.z);
        atomicAdd(dst + 3, wv * f4.w);
    }
}

// ---------------- K3: precompute gate inputs X[t,g] = x_t . Wih[g] + bih[g] + bhh[g] ----------------
__global__ void __launch_bounds__(256) k_xgemm(const int* __restrict__ loc,
                                               const float* __restrict__ emb_loc,
                                               const float* __restrict__ Wih_f,
                                               const float* __restrict__ bih_f,
                                               const float* __restrict__ bhh_f,
                                               const float* __restrict__ Wih_b,
                                               const float* __restrict__ bih_b,
                                               const float* __restrict__ bhh_b) {
    int dir = blockIdx.y;
    int t0  = blockIdx.x * 16;
    const float* Wih = dir ? Wih_b : Wih_f;
    const float* b1  = dir ? bih_b : bih_f;
    const float* b2  = dir ? bhh_b : bhh_f;
    float* Xd = g_X + (size_t)dir * LSTM_T * GATES;

    __shared__ float xs[16][L_EMB];
    __shared__ int   locv[16];
    int tid = threadIdx.x;
    if (tid < 16) {
        int t  = t0 + tid;
        int tt = dir ? (LSTM_T - 1 - t) : t;
        locv[tid] = loc[tt];
    }
    __syncthreads();
    for (int tl = 0; tl < 16; tl++)
        xs[tl][tid] = __ldg(emb_loc + (size_t)locv[tl] * L_EMB + tid);
    __syncthreads();

    for (int gq = 0; gq < 4; gq++) {
        int g = gq * 256 + tid;
        const float4* wr = (const float4*)(Wih + (size_t)g * L_EMB);
        float acc[16];
        #pragma unroll
        for (int i = 0; i < 16; i++) acc[i] = 0.0f;
        #pragma unroll 4
        for (int k4 = 0; k4 < L_EMB / 4; k4++) {
            float4 w4 = __ldg(wr + k4);
            #pragma unroll
            for (int tl = 0; tl < 16; tl++) {
                float4 x4 = ((const float4*)xs[tl])[k4];
                acc[tl] = fmaf(w4.x, x4.x, fmaf(w4.y, x4.y,
                           fmaf(w4.z, x4.z, fmaf(w4.w, x4.w, acc[tl]))));
            }
        }
        float bsum = __ldg(b1 + g) + __ldg(b2 + g);
        for (int tl = 0; tl < 16; tl++)
            Xd[(size_t)(t0 + tl) * GATES + g] = acc[tl] + bsum;
    }
}

// ---------------- K4: bidirectional LSTM recurrence (R1-proven protocol) ----------------
// grid = 16 CTAs, cluster = 8. Cluster 0 = forward, cluster 1 = backward.
#define CL  8
__global__ void __cluster_dims__(CL, 1, 1) __launch_bounds__(512, 1)
k_lstm(const float* __restrict__ Whh_f, const float* __restrict__ Whh_b,
       float* __restrict__ out) {
    // h buffer: 4 quarters of 64 floats, padded to stride 68 (bank-conflict-free)
    __shared__ float h_s[2][4 * 68];
    __shared__ float gates_s[128];

    int dir = blockIdx.x / CL;
    uint32_t r;
    asm("mov.u32 %0, %%cluster_ctarank;" : "=r"(r));

    const float* Whh = dir ? Whh_b : Whh_f;
    const float* Xd  = g_X + (size_t)dir * LSTM_T * GATES;

    int tid = threadIdx.x;
    int gi  = tid >> 2;            // 0..127 local gate row
    int c   = tid & 3;             // column quarter (64 cols)
    int q   = gi >> 5;             // gate type i/f/g/o
    int d   = gi & 31;             // h-dim within this CTA
    int grow = q * HID + (int)r * 32 + d;   // global gate row

    // load this thread's 64 Whh weights into registers
    float w[64];
    {
        const float4* wp = (const float4*)(Whh + (size_t)grow * HID + c * 64);
        #pragma unroll
        for (int i = 0; i < 16; i++) {
            float4 t4 = __ldg(wp + i);
            w[4 * i + 0] = t4.x; w[4 * i + 1] = t4.y;
            w[4 * i + 2] = t4.z; w[4 * i + 3] = t4.w;
        }
    }

    for (int i = tid; i < 2 * 4 * 68; i += blockDim.x)
        (&h_s[0][0])[i] = 0.0f;
    float creg = 0.0f;
    __syncthreads();
    CLUSTER_SYNC();   // all buffers zeroed before any peer writes

    float xcur = (c == 0) ? __ldg(Xd + grow) : 0.0f;
    int bufp = 0;
    for (int t = 0; t < LSTM_T; t++) {
        // prefetch next-step gate input (off the critical path)
        float xnext = 0.0f;
        if (c == 0 && t + 1 < LSTM_T)
            xnext = __ldg(Xd + (size_t)(t + 1) * GATES + grow);

        const float4* hp = (const float4*)(h_s[bufp] + c * 68);
        float a0 = 0.f, a1 = 0.f, a2 = 0.f, a3 = 0.f;
        #pragma unroll
        for (int i = 0; i < 16; i++) {
            float4 hv = hp[i];
            a0 = fmaf(w[4 * i + 0], hv.x, a0);
            a1 = fmaf(w[4 * i + 1], hv.y, a1);
            a2 = fmaf(w[4 * i + 2], hv.z, a2);
            a3 = fmaf(w[4 * i + 3], hv.w, a3);
        }
        float v = (a0 + a1) + (a2 + a3);
        v += __shfl_xor_sync(0xffffffffu, v, 1);
        v += __shfl_xor_sync(0xffffffffu, v, 2);
        if (c == 0) gates_s[gi] = v + xcur;
        __syncthreads();

        int bufn = bufp ^ 1;
        if (tid < 32) {
            float iv = fsig(gates_s[tid]);
            float fv = fsig(gates_s[32 + tid]);
            float gv = ftanh(gates_s[64 + tid]);
            float ov = fsig(gates_s[96 + tid]);
            creg = fv * creg + iv * gv;
            float hn = ov * ftanh(creg);

            int hidx = (int)r * 32 + tid;   // global h index 0..255
            size_t orow = (dir == 0)
                        ? (size_t)t * (2 * HID) + hidx
                        : (size_t)(LSTM_T - 1 - t) * (2 * HID) + HID + hidx;
            out[orow] = hn;
            if (t == LSTM_T - 1) {
                out[H1_OFF + (size_t)dir * HID + hidx] = hn;
                out[C1_OFF + (size_t)dir * HID + hidx] = creg;
            }

            // broadcast hn into every cluster CTA's next h buffer (scalar, R1-proven)
            int quarter = hidx >> 6;
            int pos     = hidx & 63;
            uint32_t laddr = smem_u32(&h_s[bufn][quarter * 68 + pos]);
            #pragma unroll
            for (int p = 0; p < CL; p++) {
                uint32_t pa;
                asm volatile("mapa.shared::cluster.u32 %0, %1, %2;"
                             : "=r"(pa) : "r"(laddr), "r"(p));
                asm volatile("st.shared::cluster.f32 [%0], %1;"
                             :: "r"(pa), "f"(hn) : "memory");
            }
        }
        CLUSTER_SYNC();
        bufp = bufn;
        xcur = xnext;
    }
}

// ---------------- K5: relu(aggF @ gc_w + b), mean-accumulate ----------------
__global__ void __launch_bounds__(512) k_gcn_gemm(const float* __restrict__ gc_w,
                                                  const float* __restrict__ gc_b) {
    __shared__ float a_sh[8][G_EMB];   // 8-node tile of aggF
    __shared__ float ps[8][HID];       // k-split partials
    int tid = threadIdx.x;
    int col = tid & 255;
    int kh  = tid >> 8;                // k-half 0/1
    float wcol[64];
    #pragma unroll
    for (int k = 0; k < 64; k++)
        wcol[k] = __ldg(gc_w + (size_t)(kh * 64 + k) * HID + col);
    float bj = __ldg(gc_b + col);

    int nblk   = gridDim.x;
    int npc    = (N_NODES + nblk - 1) / nblk;
    int nstart = blockIdx.x * npc;
    int nend   = min(nstart + npc, N_NODES);

    float msum = 0.0f;
    for (int n0 = nstart; n0 < nend; n0 += 8) {
        int tn = min(8, nend - n0);
        __syncthreads();
        if (tid < 256) {
            int node = tid >> 5, k4 = tid & 31;
            float4 v = make_float4(0.f, 0.f, 0.f, 0.f);
            if (node < tn)
                v = __ldg((const float4*)(g_aggF + (size_t)(n0 + node) * G_EMB) + k4);
            ((float4*)a_sh[node])[k4] = v;
        }
        __syncthreads();

        float acc[8];
        #pragma unroll
        for (int i = 0; i < 8; i++) acc[i] = 0.0f;
        #pragma unroll
        for (int k4 = 0; k4 < 16; k4++) {
            #pragma unroll
            for (int i = 0; i < 8; i++) {
                float4 av = ((const float4*)a_sh[i])[kh * 16 + k4];
                acc[i] = fmaf(av.x, wcol[4 * k4 + 0],
                         fmaf(av.y, wcol[4 * k4 + 1],
                         fmaf(av.z, wcol[4 * k4 + 2],
                         fmaf(av.w, wcol[4 * k4 + 3], acc[i]))));
            }
        }
        if (kh == 1) {
            #pragma unroll
            for (int i = 0; i < 8; i++) ps[i][col] = acc[i];
        }
        __syncthreads();
        if (kh == 0) {
            #pragma unroll
            for (int i = 0; i < 8; i++)
                if (i < tn)
                    msum += fmaxf(acc[i] + ps[i][col] + bj, 0.0f);
        }
    }
    if (kh == 0) atomicAdd(&g_gcn_sum[col], msum);
}

// ---------------- K6: finalize gcn mean ----------------
__global__ void k_gcn_final(float* __restrict__ out) {
    int tid = threadIdx.x;
    if (tid < HID)
        out[GCN_OFF + tid] = g_gcn_sum[tid] * (1.0f / (float)N_NODES);
}

// ---------------- launch ----------------
extern "C" void kernel_launch(void* const* d_in, const int* in_sizes, int n_in,
                              void* d_out, int out_size) {
    int o = (n_in > 4 && in_sizes[4] == 1) ? 1 : 0;
    const int*   loc           = (const int*)  d_in[0];
    const int*   loc_train     = (const int*)  d_in[1];
    const int*   edge_index    = (const int*)  d_in[2];
    const float* edge_weight   = (const float*)d_in[3];
    const float* emb_loc       = (const float*)d_in[4 + o];
    const float* emb_loc_graph = (const float*)d_in[5 + o];
    const float* gc_w          = (const float*)d_in[6 + o];
    const float* gc_b          = (const float*)d_in[7 + o];
    const float* Wih_f         = (const float*)d_in[8 + o];
    const float* Whh_f         = (const float*)d_in[9 + o];
    const float* bih_f         = (const float*)d_in[10 + o];
    const float* bhh_f         = (const float*)d_in[11 + o];
    const float* Wih_b         = (const float*)d_in[12 + o];
    const float* Whh_b         = (const float*)d_in[13 + o];
    const float* bih_b         = (const float*)d_in[14 + o];
    const float* bhh_b         = (const float*)d_in[15 + o];
    float* out = (float*)d_out;

    k_zero<<<256, 256>>>();
    k_edge_scatter<<<2048, 256>>>(edge_index, edge_weight, loc_train, emb_loc_graph);
    k_xgemm<<<dim3(LSTM_T / 16, 2), 256>>>(loc, emb_loc,
                                           Wih_f, bih_f, bhh_f,
                                           Wih_b, bih_b, bhh_b);
    k_lstm<<<16, 512>>>(Whh_f, Whh_b, out);
    k_gcn_gemm<<<148, 512>>>(gc_w, gc_b);
    k_gcn_final<<<1, 256>>>(out);
}